// round 16
// baseline (speedup 1.0000x reference)
#include <cuda_runtime.h>
#include <cuda_bf16.h>
#include <cuda_fp16.h>
#include <math_constants.h>
#include <cstdint>

#define BB 8
#define N1C 2048
#define N2C 2048
#define DD 120
#define NROWS (BB * N1C)
#define OSZ ((size_t)BB * N1C * DD)

// ---------------- scratch (device globals; no allocation) ----------------
__device__ uint32_t g_Qh[(size_t)NROWS * 64];            // [row][w] fp16x2 hi pairs (w 60..63 zero)
__device__ uint32_t g_Ql[(size_t)NROWS * 64];            // [row][w] fp16x2 lo pairs
__device__ uint32_t g_Kh[(size_t)NROWS * 64];            // [row][w] fp16x2 hi pairs (w 60..63 zero)
__device__ uint32_t g_Kl[(size_t)NROWS * 64];            // [row][w] fp16x2 lo pairs
__device__ uint32_t g_Vhw[(size_t)BB * DD * (N2C / 2)];  // [b][e][j2] fp16x2 (hi only)
__device__ uint32_t g_U[(size_t)BB * N1C * (N2C / 2)];   // [row][j2] fp16x2 u = exp(s - m_tile)
__device__ float    g_Mt[(size_t)32 * NROWS];            // per (jh*16+t) per row: tile max
__device__ float    g_M2[2 * NROWS];                     // per-half row max
__device__ float    g_L2[2 * NROWS];                     // per-half row sum-exp
__device__ float    g_Op[2 * OSZ];                       // per-half partial O

// ---------------- mma helper ----------------
__device__ __forceinline__ void mma_f16(float* c,
    uint32_t a0, uint32_t a1, uint32_t a2, uint32_t a3,
    uint32_t b0, uint32_t b1)
{
    asm volatile(
        "mma.sync.aligned.m16n8k16.row.col.f32.f16.f16.f32 "
        "{%0,%1,%2,%3}, {%4,%5,%6,%7}, {%8,%9}, {%0,%1,%2,%3};"
        : "+f"(c[0]), "+f"(c[1]), "+f"(c[2]), "+f"(c[3])
        : "r"(a0), "r"(a1), "r"(a2), "r"(a3), "r"(b0), "r"(b1));
}

// two fp32 -> packed fp16x2 hi + fp16x2 lo (x0 in low half)
__device__ __forceinline__ void hsplit2(float x0, float x1, uint32_t& h, uint32_t& l) {
    __half2 hh = __floats2half2_rn(x0, x1);
    float2 hf = __half22float2(hh);
    __half2 ll = __floats2half2_rn(x0 - hf.x, x1 - hf.y);
    h = *(uint32_t*)&hh;
    l = *(uint32_t*)&ll;
}

// ================= kernel 1: QKV projection via fp16 split mma =================
#define PJ_WH 0
#define PJ_WL 8704
#define PJ_XH 17408
#define PJ_XL 21760
#define PJ_DS 17408
#define PJ_SMEM (26112 * 4)     // 104448 B -> 2 blocks/SM

__global__ __launch_bounds__(256, 2) void proj_kernel(
    const float* __restrict__ x1, const float* __restrict__ x2,
    const float* __restrict__ Wq, const float* __restrict__ Wk,
    const float* __restrict__ Wv)
{
    extern __shared__ float smf[];
    uint32_t* Wth = (uint32_t*)smf + PJ_WH;
    uint32_t* Wtl = (uint32_t*)smf + PJ_WL;
    uint32_t* Xh  = (uint32_t*)smf + PJ_XH;
    uint32_t* Xl  = (uint32_t*)smf + PJ_XL;
    float*    Ds  = smf + PJ_DS;

    const int which = blockIdx.y;
    const float* X = (which == 0) ? x1 : x2;
    const float* W = (which == 0) ? Wq : (which == 1 ? Wk : Wv);

    const int row0 = blockIdx.x * 64;
    const int tid  = threadIdx.x;
    const int wid  = tid >> 5;
    const int lane = tid & 31;
    const int g    = lane >> 2;
    const int tig  = lane & 3;
    const int m0 = 32 * (wid >> 2);
    const int n0 = 32 * (wid & 3);

    // zero pads
    for (int idx = tid; idx < 512; idx += 256) {
        int r = idx >> 2, w = 60 + (idx & 3);
        Wth[r * 68 + w] = 0u; Wtl[r * 68 + w] = 0u;
    }
    for (int idx = tid; idx < 544; idx += 256) {
        int r = 120 + idx / 68, w = idx % 68;
        if (r < 128) { Wth[r * 68 + w] = 0u; Wtl[r * 68 + w] = 0u; }
    }
    if (tid < 256) {
        int r = tid >> 2, w = 60 + (tid & 3);
        Xh[r * 68 + w] = 0u; Xl[r * 68 + w] = 0u;
    }

    // stage W transposed + split
    #pragma unroll
    for (int it = 0; it < 29; it++) {
        int idx = it * 256 + tid;           // 7200 = 60 w x 120 e
        if (idx < 7200) {
            int w = idx / 120, e = idx - w * 120;
            uint32_t h, l;
            hsplit2(W[(size_t)(2 * w) * DD + e], W[(size_t)(2 * w + 1) * DD + e], h, l);
            Wth[e * 68 + w] = h;
            Wtl[e * 68 + w] = l;
        }
    }
    // stage X split
    #pragma unroll
    for (int it = 0; it < 8; it++) {
        int idx = it * 256 + tid;
        int r = idx >> 5, ch = idx & 31;
        if (ch < 30) {
            float4 v = *(const float4*)&X[(size_t)(row0 + r) * DD + ch * 4];
            uint32_t h0, l0, h1, l1;
            hsplit2(v.x, v.y, h0, l0);
            hsplit2(v.z, v.w, h1, l1);
            int base = r * 68 + ch * 2;
            Xh[base] = h0; Xh[base + 1] = h1;
            Xl[base] = l0; Xl[base + 1] = l1;
        }
    }
    __syncthreads();

    float acc[2][4][4];
    #pragma unroll
    for (int m = 0; m < 2; m++)
        #pragma unroll
        for (int n = 0; n < 4; n++)
            #pragma unroll
            for (int q = 0; q < 4; q++) acc[m][n][q] = 0.f;

    #pragma unroll
    for (int c = 0; c < 8; c++) {
        const int kw = c * 8 + tig;
        uint32_t ah[2][4], al[2][4];
        #pragma unroll
        for (int m = 0; m < 2; m++) {
            int r0 = (m0 + 16 * m + g) * 68 + kw;
            int r1 = r0 + 8 * 68;
            ah[m][0] = Xh[r0]; ah[m][1] = Xh[r1];
            ah[m][2] = Xh[r0 + 4]; ah[m][3] = Xh[r1 + 4];
            al[m][0] = Xl[r0]; al[m][1] = Xl[r1];
            al[m][2] = Xl[r0 + 4]; al[m][3] = Xl[r1 + 4];
        }
        #pragma unroll
        for (int n = 0; n < 4; n++) {
            int eb = (n0 + 8 * n + g) * 68 + kw;
            uint32_t bh0 = Wth[eb], bh1 = Wth[eb + 4];
            uint32_t bl0 = Wtl[eb], bl1 = Wtl[eb + 4];
            #pragma unroll
            for (int m = 0; m < 2; m++) {
                mma_f16(acc[m][n], ah[m][0], ah[m][1], ah[m][2], ah[m][3], bh0, bh1);
                mma_f16(acc[m][n], al[m][0], al[m][1], al[m][2], al[m][3], bh0, bh1);
                mma_f16(acc[m][n], ah[m][0], ah[m][1], ah[m][2], ah[m][3], bl0, bl1);
            }
        }
    }
    __syncthreads();   // X dead; Ds aliases it

    #pragma unroll
    for (int m = 0; m < 2; m++)
        #pragma unroll
        for (int n = 0; n < 4; n++) {
            int row = m0 + 16 * m + g;
            int col = n0 + 8 * n + 2 * tig;
            *(float2*)&Ds[row * 132 + col]       = make_float2(acc[m][n][0], acc[m][n][1]);
            *(float2*)&Ds[(row + 8) * 132 + col] = make_float2(acc[m][n][2], acc[m][n][3]);
        }
    __syncthreads();

    const int b = row0 >> 11;
    if (which <= 1) {
        uint32_t* dH = which ? g_Kh : g_Qh;
        uint32_t* dL = which ? g_Kl : g_Ql;
        #pragma unroll
        for (int it = 0; it < 16; it++) {
            int idx = it * 256 + tid;
            int r = idx >> 6, w = idx & 63;
            if (w < 60) {
                uint32_t h, l;
                hsplit2(Ds[r * 132 + 2 * w], Ds[r * 132 + 2 * w + 1], h, l);
                size_t base = (size_t)(row0 + r) * 64 + w;
                dH[base] = h;
                dL[base] = l;
            }
        }
    } else {
        const int np0 = (row0 & 2047) >> 1;
        #pragma unroll
        for (int it = 0; it < 15; it++) {
            int idx = it * 256 + tid;       // 3840 = 120 e x 32 pairs
            int e = idx >> 5, p = idx & 31;
            __half2 hv = __floats2half2_rn(Ds[(2 * p) * 132 + e], Ds[(2 * p + 1) * 132 + e]);
            g_Vhw[((size_t)b * DD + e) * (N2C / 2) + np0 + p] = *(uint32_t*)&hv;
        }
    }
}

// ================= kernel 2: scores -> fp16 u + per-tile max =================
#define SC_QH 0
#define SC_QL 8704
#define SC_KH 17408
#define SC_KL 21760
#define SC_SS 17408
#define SC_SMEM ((26112) * 4)            // 104448 B -> 2 blocks/SM

__global__ __launch_bounds__(256, 2) void score_kernel(
    const int* __restrict__ mask)
{
    extern __shared__ float smf[];
    uint32_t* Qh = (uint32_t*)smf + SC_QH;
    uint32_t* Ql = (uint32_t*)smf + SC_QL;
    uint32_t* Kh = (uint32_t*)smf + SC_KH;
    uint32_t* Kl = (uint32_t*)smf + SC_KL;
    float*    Ss = smf + SC_SS;

    const int b  = blockIdx.y;
    const int i0 = blockIdx.x * 128;
    const int jh = blockIdx.z;
    const int tid  = threadIdx.x;
    const int wid  = tid >> 5;
    const int lane = tid & 31;
    const int g    = lane >> 2;
    const int tig  = lane & 3;
    const int m0 = 32 * (wid >> 1);
    const int n0 = 32 * (wid & 1);

    // stage Q: plain uint4 copies of pre-split pairs (pads zero from global)
    {
        const uint4* gQh4 = (const uint4*)g_Qh;
        const uint4* gQl4 = (const uint4*)g_Ql;
        size_t gb = ((size_t)(b * N1C) + i0) * 16;
        #pragma unroll
        for (int it = 0; it < 8; it++) {
            int idx = it * 256 + tid;
            int r = idx >> 4, w4 = idx & 15;
            *(uint4*)&Qh[r * 68 + w4 * 4] = gQh4[gb + r * 16 + w4];
        }
        #pragma unroll
        for (int it = 0; it < 8; it++) {
            int idx = it * 256 + tid;
            int r = idx >> 4, w4 = idx & 15;
            *(uint4*)&Ql[r * 68 + w4 * 4] = gQl4[gb + r * 16 + w4];
        }
    }

    const float scale = 0.09128709291752768f;  // 1/sqrt(120)
    // epilogue mapping: 2 threads per row
    const int r_ep = tid >> 1;                 // 0..127
    const int h_ep = tid & 1;                  // 32-col half
    const int gi_ep = b * N1C + i0 + r_ep;
    float mrun = -CUDART_INF_F, lrun = 0.f;

    const uint4* gKh4 = (const uint4*)g_Kh;
    const uint4* gKl4 = (const uint4*)g_Kl;

    for (int t = 0; t < 16; t++) {
        const int j0 = jh * 1024 + t * 64;
        __syncthreads();                  // prior epilogue done (Ss aliases K)
        // stage K tile: plain uint4 copies (incl zero pads -> cleans Ss alias)
        {
            size_t gb = ((size_t)(b * N2C) + j0) * 16;
            #pragma unroll
            for (int it = 0; it < 4; it++) {
                int idx = it * 256 + tid;
                int r = idx >> 4, w4 = idx & 15;
                *(uint4*)&Kh[r * 68 + w4 * 4] = gKh4[gb + r * 16 + w4];
            }
            #pragma unroll
            for (int it = 0; it < 4; it++) {
                int idx = it * 256 + tid;
                int r = idx >> 4, w4 = idx & 15;
                *(uint4*)&Kl[r * 68 + w4 * 4] = gKl4[gb + r * 16 + w4];
            }
        }
        __syncthreads();

        float acc[2][4][4];
        #pragma unroll
        for (int m = 0; m < 2; m++)
            #pragma unroll
            for (int n = 0; n < 4; n++)
                #pragma unroll
                for (int q = 0; q < 4; q++) acc[m][n][q] = 0.f;

        #pragma unroll
        for (int c = 0; c < 8; c++) {
            const int kw = c * 8 + tig;
            uint32_t ah[2][4], al[2][4];
            #pragma unroll
            for (int m = 0; m < 2; m++) {
                int r0 = (m0 + 16 * m + g) * 68 + kw;
                int r1 = r0 + 8 * 68;
                ah[m][0] = Qh[r0]; ah[m][1] = Qh[r1];
                ah[m][2] = Qh[r0 + 4]; ah[m][3] = Qh[r1 + 4];
                al[m][0] = Ql[r0]; al[m][1] = Ql[r1];
                al[m][2] = Ql[r0 + 4]; al[m][3] = Ql[r1 + 4];
            }
            #pragma unroll
            for (int n = 0; n < 4; n++) {
                int kb = (n0 + 8 * n + g) * 68 + kw;
                uint32_t bh0 = Kh[kb], bh1 = Kh[kb + 4];
                uint32_t bl0 = Kl[kb], bl1 = Kl[kb + 4];
                #pragma unroll
                for (int m = 0; m < 2; m++) {
                    mma_f16(acc[m][n], ah[m][0], ah[m][1], ah[m][2], ah[m][3], bh0, bh1);
                    mma_f16(acc[m][n], al[m][0], al[m][1], al[m][2], al[m][3], bh0, bh1);
                    mma_f16(acc[m][n], ah[m][0], ah[m][1], ah[m][2], ah[m][3], bl0, bl1);
                }
            }
        }

        __syncthreads();                  // all warps done reading K before Ss overwrite

        // stage D to Ss (aliased onto K region)
        #pragma unroll
        for (int m = 0; m < 2; m++)
            #pragma unroll
            for (int n = 0; n < 4; n++) {
                int row = m0 + 16 * m + g;
                int col = n0 + 8 * n + 2 * tig;
                *(float2*)&Ss[row * 68 + col]       = make_float2(acc[m][n][0], acc[m][n][1]);
                *(float2*)&Ss[(row + 8) * 68 + col] = make_float2(acc[m][n][2], acc[m][n][3]);
            }
        __syncthreads();

        // epilogue (2 threads per row): mask+scale into 32 regs, single-shfl max,
        // u = exp(s - mt), single-shfl sum, coalesced uint4 u stores
        {
            float s[32];
            const float* srow = &Ss[r_ep * 68 + h_ep * 32];
            size_t mb = (size_t)gi_ep * N2C + j0 + h_ep * 32;
            #pragma unroll
            for (int q = 0; q < 8; q++) {
                float4 sv = *(const float4*)&srow[4 * q];
                int4 mv = *(const int4*)&mask[mb + 4 * q];
                s[4 * q + 0] = mv.x ? sv.x * scale : -CUDART_INF_F;
                s[4 * q + 1] = mv.y ? sv.y * scale : -CUDART_INF_F;
                s[4 * q + 2] = mv.z ? sv.z * scale : -CUDART_INF_F;
                s[4 * q + 3] = mv.w ? sv.w * scale : -CUDART_INF_F;
            }
            float tmax = s[0];
            #pragma unroll
            for (int q = 1; q < 32; q++) tmax = fmaxf(tmax, s[q]);
            tmax = fmaxf(tmax, __shfl_xor_sync(0xffffffffu, tmax, 1));
            float mt = fmaxf(tmax, -1e30f);

            float su = 0.f;
            #pragma unroll
            for (int q = 0; q < 32; q++) {
                s[q] = __expf(s[q] - mt);
                su += s[q];
            }
            su += __shfl_xor_sync(0xffffffffu, su, 1);

            uint32_t uw[16];
            #pragma unroll
            for (int q = 0; q < 16; q++) {
                __half2 hv = __floats2half2_rn(s[2 * q], s[2 * q + 1]);
                uw[q] = *(uint32_t*)&hv;
            }
            uint4* dst = (uint4*)&g_U[(size_t)gi_ep * (N2C / 2) + (j0 >> 1) + h_ep * 16];
            #pragma unroll
            for (int q = 0; q < 4; q++)
                dst[q] = make_uint4(uw[4 * q], uw[4 * q + 1], uw[4 * q + 2], uw[4 * q + 3]);

            float mnew = fmaxf(mrun, mt);
            lrun = lrun * __expf(fmaxf(mrun - mnew, -88.f))
                 + su * __expf(fmaxf(mt - mnew, -88.f));
            mrun = mnew;

            if (h_ep == 0)
                g_Mt[((size_t)(jh * 16 + t)) * NROWS + gi_ep] = mt;
        }
    }

    // per-half stats write (one thread per row)
    if (h_ep == 0) {
        g_M2[jh * NROWS + gi_ep] = mrun;
        g_L2[jh * NROWS + gi_ep] = lrun;
    }
}

// ================= kernel 3: attn finalize + partial O = P.V (fp16 1-chain) =================
// smem words: Ph[128][36], Vh[128][36], mrow[128], lirow[128], fs[128]
#define PV_VH_OFF (128 * 36)
#define PV_MR_OFF (PV_VH_OFF + 128 * 36)
#define PV_SMEM ((PV_MR_OFF + 384) * 4)   // 38400 B -> 2 blocks/SM

__global__ __launch_bounds__(256, 2) void pv_kernel(
    float* __restrict__ attn)
{
    extern __shared__ float sm[];
    uint32_t* Ph = (uint32_t*)sm;
    uint32_t* Vh = (uint32_t*)sm + PV_VH_OFF;
    float* mrow  = sm + PV_MR_OFF;
    float* lirow = mrow + 128;
    float* fs    = lirow + 128;

    const int b  = blockIdx.y;
    const int i0 = blockIdx.x * 128;
    const int jh = blockIdx.z;
    const int tid  = threadIdx.x;
    const int wid  = tid >> 5;
    const int lane = tid & 31;
    const int g    = lane >> 2;
    const int tig  = lane & 3;
    const int m0 = 32 * (wid >> 1);
    const int e0 = 64 * (wid & 1);

    // merge the two halves' softmax stats
    if (tid < 128) {
        int gi = b * N1C + i0 + tid;
        float ma = g_M2[gi],          mb_ = g_M2[NROWS + gi];
        float la = g_L2[gi],          lb  = g_L2[NROWS + gi];
        float m = fmaxf(ma, mb_);
        float l = la * __expf(fmaxf(ma - m, -88.f)) + lb * __expf(fmaxf(mb_ - m, -88.f));
        mrow[tid]  = m;
        lirow[tid] = 1.0f / l;
    }
    // zero V rows 120..127
    for (int i = tid; i < 8 * 36; i += 256) {
        Vh[(120 + i / 36) * 36 + (i % 36)] = 0u;
    }

    float acc[2][8][4];
    #pragma unroll
    for (int m = 0; m < 2; m++)
        #pragma unroll
        for (int n = 0; n < 8; n++)
            #pragma unroll
            for (int q = 0; q < 4; q++) acc[m][n][q] = 0.f;

    const uint4* gV4 = (const uint4*)g_Vhw;
    const uint4* gU4 = (const uint4*)g_U;

    for (int t = 0; t < 16; t++) {
        const int j0 = jh * 1024 + t * 64;

        // stage per-row tile correction factors
        if (tid < 128) {
            int gi = b * N1C + i0 + tid;
            float mt = g_Mt[((size_t)(jh * 16 + t)) * NROWS + gi];
            fs[tid] = __expf(fmaxf(mt - mrow[tid], -88.f)) * lirow[tid];
        }
        __syncthreads();

        // V stage: uint4 copy of pre-split fp16 pairs
        {
            size_t gb = ((size_t)b * DD) * (N2C / 8) + (j0 >> 3);
            #pragma unroll
            for (int it = 0; it < 4; it++) {
                int idx = it * 256 + tid;     // 960: 120 e x 8 uint4
                int e = idx >> 3, w4 = idx & 7;
                if (idx < 960)
                    *(uint4*)&Vh[e * 36 + w4 * 4] = gV4[gb + (size_t)e * (N2C / 8) + w4];
            }
        }

        // P stage (8-wide): uint4 u load, p = u * fs[r]; attn write + Ph pack
        #pragma unroll
        for (int it = 0; it < 4; it++) {
            int idx = it * 256 + tid;         // 1024: 128 rows x 8 col-groups
            int r  = idx >> 3;
            int c8 = (idx & 7) * 8;
            int gi = b * N1C + i0 + r;
            uint4 uw = gU4[(size_t)gi * (N2C / 8) + ((j0 + c8) >> 3)];
            float2 f0 = __half22float2(*(__half2*)&uw.x);
            float2 f1 = __half22float2(*(__half2*)&uw.y);
            float2 f2 = __half22float2(*(__half2*)&uw.z);
            float2 f3 = __half22float2(*(__half2*)&uw.w);
            float f = fs[r];
            float4 pa = make_float4(f0.x * f, f0.y * f, f1.x * f, f1.y * f);
            float4 pb = make_float4(f2.x * f, f2.y * f, f3.x * f, f3.y * f);
            size_t ab = (size_t)gi * N2C + j0 + c8;
            *(float4*)&attn[ab]     = pa;
            *(float4*)&attn[ab + 4] = pb;
            __half2 q0 = __floats2half2_rn(pa.x, pa.y);
            __half2 q1 = __floats2half2_rn(pa.z, pa.w);
            __half2 q2 = __floats2half2_rn(pb.x, pb.y);
            __half2 q3 = __floats2half2_rn(pb.z, pb.w);
            *(uint4*)&Ph[r * 36 + (c8 >> 1)] =
                make_uint4(*(uint32_t*)&q0, *(uint32_t*)&q1,
                           *(uint32_t*)&q2, *(uint32_t*)&q3);
        }
        __syncthreads();

        // mainloop: 4 k16 chunks over j, single fp16 chain
        #pragma unroll
        for (int c = 0; c < 4; c++) {
            const int kb2 = c * 8;
            uint32_t ah[2][4];
            #pragma unroll
            for (int m = 0; m < 2; m++) {
                int ra = (m0 + 16 * m + g) * 36 + kb2 + tig;
                int rb = (m0 + 16 * m + 8 + g) * 36 + kb2 + tig;
                ah[m][0] = Ph[ra]; ah[m][1] = Ph[rb];
                ah[m][2] = Ph[ra + 4]; ah[m][3] = Ph[rb + 4];
            }
            #pragma unroll
            for (int n = 0; n < 8; n++) {
                int e = e0 + 8 * n + g;
                int vb = e * 36 + kb2 + tig;
                uint32_t bh0 = Vh[vb], bh1 = Vh[vb + 4];
                #pragma unroll
                for (int m = 0; m < 2; m++) {
                    mma_f16(acc[m][n], ah[m][0], ah[m][1], ah[m][2], ah[m][3], bh0, bh1);
                }
            }
        }
    }

    // partial O store to this half's buffer
    float* op = g_Op + (size_t)jh * OSZ;
    #pragma unroll
    for (int m = 0; m < 2; m++)
        #pragma unroll
        for (int n = 0; n < 8; n++) {
            int e = e0 + 8 * n + 2 * tig;
            if (e < DD) {
                int i = i0 + m0 + 16 * m + g;
                *(float2*)&op[((size_t)(b * N1C + i)) * DD + e] =
                    make_float2(acc[m][n][0], acc[m][n][1]);
                *(float2*)&op[((size_t)(b * N1C + i + 8)) * DD + e] =
                    make_float2(acc[m][n][2], acc[m][n][3]);
            }
        }
}

// ================= kernel 4: merge the two O halves =================
__global__ __launch_bounds__(256) void omerge_kernel(float* __restrict__ out)
{
    size_t idx = ((size_t)blockIdx.x * 256 + threadIdx.x) * 4;
    if (idx < OSZ) {
        float4 a = *(const float4*)&g_Op[idx];
        float4 c = *(const float4*)&g_Op[OSZ + idx];
        a.x += c.x; a.y += c.y; a.z += c.z; a.w += c.w;
        *(float4*)&out[idx] = a;
    }
}

// ================= launch =================
extern "C" void kernel_launch(void* const* d_in, const int* in_sizes, int n_in,
                              void* d_out, int out_size)
{
    const float* x1  = (const float*)d_in[0];
    const float* x2  = (const float*)d_in[1];
    const int*   msk = (const int*)  d_in[2];
    const float* Wq  = (const float*)d_in[3];
    const float* Wk  = (const float*)d_in[4];
    const float* Wv  = (const float*)d_in[5];

    float* outO = (float*)d_out;                    // [B,N1,D]
    float* outP = outO + OSZ;                       // [B,N1,N2]

    cudaFuncSetAttribute(proj_kernel,  cudaFuncAttributeMaxDynamicSharedMemorySize, PJ_SMEM);
    cudaFuncSetAttribute(score_kernel, cudaFuncAttributeMaxDynamicSharedMemorySize, SC_SMEM);
    cudaFuncSetAttribute(pv_kernel,    cudaFuncAttributeMaxDynamicSharedMemorySize, PV_SMEM);

    proj_kernel <<<dim3(NROWS / 64, 3), 256, PJ_SMEM>>>(x1, x2, Wq, Wk, Wv);
    score_kernel<<<dim3(N1C / 128, BB, 2), 256, SC_SMEM>>>(msk);
    pv_kernel   <<<dim3(N1C / 128, BB, 2), 256, PV_SMEM>>>(outP);
    omerge_kernel<<<(int)((OSZ / 4 + 255) / 256), 256>>>(outO);
}

// round 17
// speedup vs baseline: 1.1712x; 1.1712x over previous
#include <cuda_runtime.h>
#include <cuda_bf16.h>
#include <cuda_fp16.h>
#include <math_constants.h>
#include <cstdint>

#define BB 8
#define N1C 2048
#define N2C 2048
#define DD 120
#define NROWS (BB * N1C)
#define OSZ ((size_t)BB * N1C * DD)

// ---------------- scratch (device globals; no allocation) ----------------
__device__ uint32_t g_Qh[(size_t)NROWS * 64];            // [row][w] fp16x2 hi pairs (w 60..63 zero)
__device__ uint32_t g_Ql[(size_t)NROWS * 64];            // [row][w] fp16x2 lo pairs
__device__ uint32_t g_Kh[(size_t)NROWS * 64];            // [row][w] fp16x2 hi pairs (w 60..63 zero)
__device__ uint32_t g_Kl[(size_t)NROWS * 64];            // [row][w] fp16x2 lo pairs
__device__ uint32_t g_Vhw[(size_t)BB * DD * (N2C / 2)];  // [b][e][j2] fp16x2 (hi only)
__device__ uint32_t g_U[(size_t)BB * N1C * (N2C / 2)];   // [row][j2] fp16x2 u = exp(s - m_tile)
__device__ float    g_Mt[(size_t)32 * NROWS];            // per (jh*16+t) per row: tile max
__device__ float    g_M2[2 * NROWS];                     // per-half row max
__device__ float    g_L2[2 * NROWS];                     // per-half row sum-exp
__device__ float    g_Op[2 * OSZ];                       // per-half partial O

// ---------------- mma helper ----------------
__device__ __forceinline__ void mma_f16(float* c,
    uint32_t a0, uint32_t a1, uint32_t a2, uint32_t a3,
    uint32_t b0, uint32_t b1)
{
    asm volatile(
        "mma.sync.aligned.m16n8k16.row.col.f32.f16.f16.f32 "
        "{%0,%1,%2,%3}, {%4,%5,%6,%7}, {%8,%9}, {%0,%1,%2,%3};"
        : "+f"(c[0]), "+f"(c[1]), "+f"(c[2]), "+f"(c[3])
        : "r"(a0), "r"(a1), "r"(a2), "r"(a3), "r"(b0), "r"(b1));
}

// two fp32 -> packed fp16x2 hi + fp16x2 lo (x0 in low half)
__device__ __forceinline__ void hsplit2(float x0, float x1, uint32_t& h, uint32_t& l) {
    __half2 hh = __floats2half2_rn(x0, x1);
    float2 hf = __half22float2(hh);
    __half2 ll = __floats2half2_rn(x0 - hf.x, x1 - hf.y);
    h = *(uint32_t*)&hh;
    l = *(uint32_t*)&ll;
}

// ================= kernel 1: QKV projection via fp16 split mma =================
#define PJ_WH 0
#define PJ_WL 8704
#define PJ_XH 17408
#define PJ_XL 21760
#define PJ_DS 17408
#define PJ_SMEM (26112 * 4)     // 104448 B -> 2 blocks/SM

__global__ __launch_bounds__(256, 2) void proj_kernel(
    const float* __restrict__ x1, const float* __restrict__ x2,
    const float* __restrict__ Wq, const float* __restrict__ Wk,
    const float* __restrict__ Wv)
{
    extern __shared__ float smf[];
    uint32_t* Wth = (uint32_t*)smf + PJ_WH;
    uint32_t* Wtl = (uint32_t*)smf + PJ_WL;
    uint32_t* Xh  = (uint32_t*)smf + PJ_XH;
    uint32_t* Xl  = (uint32_t*)smf + PJ_XL;
    float*    Ds  = smf + PJ_DS;

    const int which = blockIdx.y;
    const float* X = (which == 0) ? x1 : x2;
    const float* W = (which == 0) ? Wq : (which == 1 ? Wk : Wv);

    const int row0 = blockIdx.x * 64;
    const int tid  = threadIdx.x;
    const int wid  = tid >> 5;
    const int lane = tid & 31;
    const int g    = lane >> 2;
    const int tig  = lane & 3;
    const int m0 = 32 * (wid >> 2);
    const int n0 = 32 * (wid & 3);

    // zero pads
    for (int idx = tid; idx < 512; idx += 256) {
        int r = idx >> 2, w = 60 + (idx & 3);
        Wth[r * 68 + w] = 0u; Wtl[r * 68 + w] = 0u;
    }
    for (int idx = tid; idx < 544; idx += 256) {
        int r = 120 + idx / 68, w = idx % 68;
        if (r < 128) { Wth[r * 68 + w] = 0u; Wtl[r * 68 + w] = 0u; }
    }
    if (tid < 256) {
        int r = tid >> 2, w = 60 + (tid & 3);
        Xh[r * 68 + w] = 0u; Xl[r * 68 + w] = 0u;
    }

    // stage W transposed + split
    #pragma unroll
    for (int it = 0; it < 29; it++) {
        int idx = it * 256 + tid;           // 7200 = 60 w x 120 e
        if (idx < 7200) {
            int w = idx / 120, e = idx - w * 120;
            uint32_t h, l;
            hsplit2(W[(size_t)(2 * w) * DD + e], W[(size_t)(2 * w + 1) * DD + e], h, l);
            Wth[e * 68 + w] = h;
            Wtl[e * 68 + w] = l;
        }
    }
    // stage X split
    #pragma unroll
    for (int it = 0; it < 8; it++) {
        int idx = it * 256 + tid;
        int r = idx >> 5, ch = idx & 31;
        if (ch < 30) {
            float4 v = *(const float4*)&X[(size_t)(row0 + r) * DD + ch * 4];
            uint32_t h0, l0, h1, l1;
            hsplit2(v.x, v.y, h0, l0);
            hsplit2(v.z, v.w, h1, l1);
            int base = r * 68 + ch * 2;
            Xh[base] = h0; Xh[base + 1] = h1;
            Xl[base] = l0; Xl[base + 1] = l1;
        }
    }
    __syncthreads();

    float acc[2][4][4];
    #pragma unroll
    for (int m = 0; m < 2; m++)
        #pragma unroll
        for (int n = 0; n < 4; n++)
            #pragma unroll
            for (int q = 0; q < 4; q++) acc[m][n][q] = 0.f;

    #pragma unroll
    for (int c = 0; c < 8; c++) {
        const int kw = c * 8 + tig;
        uint32_t ah[2][4], al[2][4];
        #pragma unroll
        for (int m = 0; m < 2; m++) {
            int r0 = (m0 + 16 * m + g) * 68 + kw;
            int r1 = r0 + 8 * 68;
            ah[m][0] = Xh[r0]; ah[m][1] = Xh[r1];
            ah[m][2] = Xh[r0 + 4]; ah[m][3] = Xh[r1 + 4];
            al[m][0] = Xl[r0]; al[m][1] = Xl[r1];
            al[m][2] = Xl[r0 + 4]; al[m][3] = Xl[r1 + 4];
        }
        #pragma unroll
        for (int n = 0; n < 4; n++) {
            int eb = (n0 + 8 * n + g) * 68 + kw;
            uint32_t bh0 = Wth[eb], bh1 = Wth[eb + 4];
            uint32_t bl0 = Wtl[eb], bl1 = Wtl[eb + 4];
            #pragma unroll
            for (int m = 0; m < 2; m++) {
                mma_f16(acc[m][n], ah[m][0], ah[m][1], ah[m][2], ah[m][3], bh0, bh1);
                mma_f16(acc[m][n], al[m][0], al[m][1], al[m][2], al[m][3], bh0, bh1);
                mma_f16(acc[m][n], ah[m][0], ah[m][1], ah[m][2], ah[m][3], bl0, bl1);
            }
        }
    }
    __syncthreads();   // X dead; Ds aliases it

    #pragma unroll
    for (int m = 0; m < 2; m++)
        #pragma unroll
        for (int n = 0; n < 4; n++) {
            int row = m0 + 16 * m + g;
            int col = n0 + 8 * n + 2 * tig;
            *(float2*)&Ds[row * 132 + col]       = make_float2(acc[m][n][0], acc[m][n][1]);
            *(float2*)&Ds[(row + 8) * 132 + col] = make_float2(acc[m][n][2], acc[m][n][3]);
        }
    __syncthreads();

    const int b = row0 >> 11;
    if (which <= 1) {
        uint32_t* dH = which ? g_Kh : g_Qh;
        uint32_t* dL = which ? g_Kl : g_Ql;
        #pragma unroll
        for (int it = 0; it < 16; it++) {
            int idx = it * 256 + tid;
            int r = idx >> 6, w = idx & 63;
            if (w < 60) {
                uint32_t h, l;
                hsplit2(Ds[r * 132 + 2 * w], Ds[r * 132 + 2 * w + 1], h, l);
                size_t base = (size_t)(row0 + r) * 64 + w;
                dH[base] = h;
                dL[base] = l;
            }
        }
    } else {
        const int np0 = (row0 & 2047) >> 1;
        #pragma unroll
        for (int it = 0; it < 15; it++) {
            int idx = it * 256 + tid;       // 3840 = 120 e x 32 pairs
            int e = idx >> 5, p = idx & 31;
            __half2 hv = __floats2half2_rn(Ds[(2 * p) * 132 + e], Ds[(2 * p + 1) * 132 + e]);
            g_Vhw[((size_t)b * DD + e) * (N2C / 2) + np0 + p] = *(uint32_t*)&hv;
        }
    }
}

// ================= kernel 2: scores -> fp16 u + per-tile max =================
#define SC_QH 0
#define SC_QL 8704
#define SC_KH 17408
#define SC_KL 21760
#define SC_SS 17408
#define SC_SMEM ((26112) * 4)            // 104448 B -> 2 blocks/SM

__global__ __launch_bounds__(256, 2) void score_kernel(
    const int* __restrict__ mask)
{
    extern __shared__ float smf[];
    uint32_t* Qh = (uint32_t*)smf + SC_QH;
    uint32_t* Ql = (uint32_t*)smf + SC_QL;
    uint32_t* Kh = (uint32_t*)smf + SC_KH;
    uint32_t* Kl = (uint32_t*)smf + SC_KL;
    float*    Ss = smf + SC_SS;

    const int b  = blockIdx.y;
    const int i0 = blockIdx.x * 128;
    const int jh = blockIdx.z;
    const int tid  = threadIdx.x;
    const int wid  = tid >> 5;
    const int lane = tid & 31;
    const int g    = lane >> 2;
    const int tig  = lane & 3;
    const int m0 = 32 * (wid >> 1);
    const int n0 = 32 * (wid & 1);

    // stage Q: plain uint4 copies of pre-split pairs (pads zero from global)
    {
        const uint4* gQh4 = (const uint4*)g_Qh;
        const uint4* gQl4 = (const uint4*)g_Ql;
        size_t gb = ((size_t)(b * N1C) + i0) * 16;
        #pragma unroll
        for (int it = 0; it < 8; it++) {
            int idx = it * 256 + tid;
            int r = idx >> 4, w4 = idx & 15;
            *(uint4*)&Qh[r * 68 + w4 * 4] = gQh4[gb + r * 16 + w4];
        }
        #pragma unroll
        for (int it = 0; it < 8; it++) {
            int idx = it * 256 + tid;
            int r = idx >> 4, w4 = idx & 15;
            *(uint4*)&Ql[r * 68 + w4 * 4] = gQl4[gb + r * 16 + w4];
        }
    }

    const float scale = 0.09128709291752768f;  // 1/sqrt(120)
    const int halfid = lane >> 4;
    const int c4ep   = (lane & 15) * 4;
    float mrun[8], lrun[8];
    #pragma unroll
    for (int k = 0; k < 8; k++) { mrun[k] = -CUDART_INF_F; lrun[k] = 0.f; }

    const uint4* gKh4 = (const uint4*)g_Kh;
    const uint4* gKl4 = (const uint4*)g_Kl;

    for (int t = 0; t < 16; t++) {
        const int j0 = jh * 1024 + t * 64;
        __syncthreads();                  // prior epilogue done (Ss aliases K)
        // stage K tile: plain uint4 copies (incl zero pads -> cleans Ss alias)
        {
            size_t gb = ((size_t)(b * N2C) + j0) * 16;
            #pragma unroll
            for (int it = 0; it < 4; it++) {
                int idx = it * 256 + tid;
                int r = idx >> 4, w4 = idx & 15;
                *(uint4*)&Kh[r * 68 + w4 * 4] = gKh4[gb + r * 16 + w4];
            }
            #pragma unroll
            for (int it = 0; it < 4; it++) {
                int idx = it * 256 + tid;
                int r = idx >> 4, w4 = idx & 15;
                *(uint4*)&Kl[r * 68 + w4 * 4] = gKl4[gb + r * 16 + w4];
            }
        }
        __syncthreads();

        float acc[2][4][4];
        #pragma unroll
        for (int m = 0; m < 2; m++)
            #pragma unroll
            for (int n = 0; n < 4; n++)
                #pragma unroll
                for (int q = 0; q < 4; q++) acc[m][n][q] = 0.f;

        #pragma unroll
        for (int c = 0; c < 8; c++) {
            const int kw = c * 8 + tig;
            uint32_t ah[2][4], al[2][4];
            #pragma unroll
            for (int m = 0; m < 2; m++) {
                int r0 = (m0 + 16 * m + g) * 68 + kw;
                int r1 = r0 + 8 * 68;
                ah[m][0] = Qh[r0]; ah[m][1] = Qh[r1];
                ah[m][2] = Qh[r0 + 4]; ah[m][3] = Qh[r1 + 4];
                al[m][0] = Ql[r0]; al[m][1] = Ql[r1];
                al[m][2] = Ql[r0 + 4]; al[m][3] = Ql[r1 + 4];
            }
            #pragma unroll
            for (int n = 0; n < 4; n++) {
                int kb = (n0 + 8 * n + g) * 68 + kw;
                uint32_t bh0 = Kh[kb], bh1 = Kh[kb + 4];
                uint32_t bl0 = Kl[kb], bl1 = Kl[kb + 4];
                #pragma unroll
                for (int m = 0; m < 2; m++) {
                    mma_f16(acc[m][n], ah[m][0], ah[m][1], ah[m][2], ah[m][3], bh0, bh1);
                    mma_f16(acc[m][n], al[m][0], al[m][1], al[m][2], al[m][3], bh0, bh1);
                    mma_f16(acc[m][n], ah[m][0], ah[m][1], ah[m][2], ah[m][3], bl0, bl1);
                }
            }
        }

        __syncthreads();                  // all warps done reading K before Ss overwrite

        // stage D to Ss (aliased onto K region)
        #pragma unroll
        for (int m = 0; m < 2; m++)
            #pragma unroll
            for (int n = 0; n < 4; n++) {
                int row = m0 + 16 * m + g;
                int col = n0 + 8 * n + 2 * tig;
                *(float2*)&Ss[row * 68 + col]       = make_float2(acc[m][n][0], acc[m][n][1]);
                *(float2*)&Ss[(row + 8) * 68 + col] = make_float2(acc[m][n][2], acc[m][n][3]);
            }
        __syncthreads();

        // epilogue: mask + scale, tile-row max (cross 16 lanes), u = exp(s - mt),
        // fp16 u store, row-sum, online per-row stats
        #pragma unroll
        for (int k = 0; k < 8; k++) {
            int r = k * 16 + wid * 2 + halfid;
            int gi = b * N1C + i0 + r;
            float4 sv = *(const float4*)&Ss[r * 68 + c4ep];
            size_t mb = ((size_t)gi) * N2C + j0 + c4ep;
            int4 mv = *(const int4*)&mask[mb];
            float4 s;
            s.x = mv.x ? sv.x * scale : -CUDART_INF_F;
            s.y = mv.y ? sv.y * scale : -CUDART_INF_F;
            s.z = mv.z ? sv.z * scale : -CUDART_INF_F;
            s.w = mv.w ? sv.w * scale : -CUDART_INF_F;

            float tmax = fmaxf(fmaxf(s.x, s.y), fmaxf(s.z, s.w));
            #pragma unroll
            for (int o = 1; o < 16; o <<= 1)
                tmax = fmaxf(tmax, __shfl_xor_sync(0xffffffffu, tmax, o));
            float mt = fmaxf(tmax, -1e30f);

            float4 u;
            u.x = __expf(s.x - mt);
            u.y = __expf(s.y - mt);
            u.z = __expf(s.z - mt);
            u.w = __expf(s.w - mt);

            __half2 ua = __floats2half2_rn(u.x, u.y);
            __half2 ub = __floats2half2_rn(u.z, u.w);
            *(uint2*)&g_U[(size_t)gi * (N2C / 2) + ((j0 + c4ep) >> 1)] =
                make_uint2(*(uint32_t*)&ua, *(uint32_t*)&ub);

            float su = (u.x + u.y) + (u.z + u.w);
            #pragma unroll
            for (int o = 1; o < 16; o <<= 1)
                su += __shfl_xor_sync(0xffffffffu, su, o);

            float mnew = fmaxf(mrun[k], mt);
            lrun[k] = lrun[k] * __expf(fmaxf(mrun[k] - mnew, -88.f))
                    + su * __expf(fmaxf(mt - mnew, -88.f));
            mrun[k] = mnew;

            if ((lane & 15) == 0)
                g_Mt[((size_t)(jh * 16 + t)) * NROWS + gi] = mt;
        }
    }

    // per-half stats write
    if ((lane & 15) == 0) {
        #pragma unroll
        for (int k = 0; k < 8; k++) {
            int gi = b * N1C + i0 + k * 16 + wid * 2 + halfid;
            g_M2[jh * NROWS + gi] = mrun[k];
            g_L2[jh * NROWS + gi] = lrun[k];
        }
    }
}

// ================= kernel 3: attn finalize + partial O = P.V (fp16 1-chain) =================
// smem words: Ph[128][36], Vh[128][36], mrow[128], lirow[128], fs[128]
#define PV_VH_OFF (128 * 36)
#define PV_MR_OFF (PV_VH_OFF + 128 * 36)
#define PV_SMEM ((PV_MR_OFF + 384) * 4)   // 38400 B -> 2 blocks/SM

__global__ __launch_bounds__(256, 2) void pv_kernel(
    float* __restrict__ attn)
{
    extern __shared__ float sm[];
    uint32_t* Ph = (uint32_t*)sm;
    uint32_t* Vh = (uint32_t*)sm + PV_VH_OFF;
    float* mrow  = sm + PV_MR_OFF;
    float* lirow = mrow + 128;
    float* fs    = lirow + 128;

    const int b  = blockIdx.y;
    const int i0 = blockIdx.x * 128;
    const int jh = blockIdx.z;
    const int tid  = threadIdx.x;
    const int wid  = tid >> 5;
    const int lane = tid & 31;
    const int g    = lane >> 2;
    const int tig  = lane & 3;
    const int m0 = 32 * (wid >> 1);
    const int e0 = 64 * (wid & 1);

    // merge the two halves' softmax stats
    if (tid < 128) {
        int gi = b * N1C + i0 + tid;
        float ma = g_M2[gi],          mb_ = g_M2[NROWS + gi];
        float la = g_L2[gi],          lb  = g_L2[NROWS + gi];
        float m = fmaxf(ma, mb_);
        float l = la * __expf(fmaxf(ma - m, -88.f)) + lb * __expf(fmaxf(mb_ - m, -88.f));
        mrow[tid]  = m;
        lirow[tid] = 1.0f / l;
    }
    // zero V rows 120..127
    for (int i = tid; i < 8 * 36; i += 256) {
        Vh[(120 + i / 36) * 36 + (i % 36)] = 0u;
    }

    float acc[2][8][4];
    #pragma unroll
    for (int m = 0; m < 2; m++)
        #pragma unroll
        for (int n = 0; n < 8; n++)
            #pragma unroll
            for (int q = 0; q < 4; q++) acc[m][n][q] = 0.f;

    const uint4* gV4 = (const uint4*)g_Vhw;
    const uint4* gU4 = (const uint4*)g_U;

    for (int t = 0; t < 16; t++) {
        const int j0 = jh * 1024 + t * 64;

        // stage per-row tile correction factors
        if (tid < 128) {
            int gi = b * N1C + i0 + tid;
            float mt = g_Mt[((size_t)(jh * 16 + t)) * NROWS + gi];
            fs[tid] = __expf(fmaxf(mt - mrow[tid], -88.f)) * lirow[tid];
        }
        __syncthreads();

        // V stage: uint4 copy of pre-split fp16 pairs
        {
            size_t gb = ((size_t)b * DD) * (N2C / 8) + (j0 >> 3);
            #pragma unroll
            for (int it = 0; it < 4; it++) {
                int idx = it * 256 + tid;     // 960: 120 e x 8 uint4
                int e = idx >> 3, w4 = idx & 7;
                if (idx < 960)
                    *(uint4*)&Vh[e * 36 + w4 * 4] = gV4[gb + (size_t)e * (N2C / 8) + w4];
            }
        }

        // P stage (8-wide): uint4 u load, p = u * fs[r]; attn write + Ph pack
        #pragma unroll
        for (int it = 0; it < 4; it++) {
            int idx = it * 256 + tid;         // 1024: 128 rows x 8 col-groups
            int r  = idx >> 3;
            int c8 = (idx & 7) * 8;
            int gi = b * N1C + i0 + r;
            uint4 uw = gU4[(size_t)gi * (N2C / 8) + ((j0 + c8) >> 3)];
            float2 f0 = __half22float2(*(__half2*)&uw.x);
            float2 f1 = __half22float2(*(__half2*)&uw.y);
            float2 f2 = __half22float2(*(__half2*)&uw.z);
            float2 f3 = __half22float2(*(__half2*)&uw.w);
            float f = fs[r];
            float4 pa = make_float4(f0.x * f, f0.y * f, f1.x * f, f1.y * f);
            float4 pb = make_float4(f2.x * f, f2.y * f, f3.x * f, f3.y * f);
            size_t ab = (size_t)gi * N2C + j0 + c8;
            *(float4*)&attn[ab]     = pa;
            *(float4*)&attn[ab + 4] = pb;
            __half2 q0 = __floats2half2_rn(pa.x, pa.y);
            __half2 q1 = __floats2half2_rn(pa.z, pa.w);
            __half2 q2 = __floats2half2_rn(pb.x, pb.y);
            __half2 q3 = __floats2half2_rn(pb.z, pb.w);
            *(uint4*)&Ph[r * 36 + (c8 >> 1)] =
                make_uint4(*(uint32_t*)&q0, *(uint32_t*)&q1,
                           *(uint32_t*)&q2, *(uint32_t*)&q3);
        }
        __syncthreads();

        // mainloop: 4 k16 chunks over j, single fp16 chain
        #pragma unroll
        for (int c = 0; c < 4; c++) {
            const int kb2 = c * 8;
            uint32_t ah[2][4];
            #pragma unroll
            for (int m = 0; m < 2; m++) {
                int ra = (m0 + 16 * m + g) * 36 + kb2 + tig;
                int rb = (m0 + 16 * m + 8 + g) * 36 + kb2 + tig;
                ah[m][0] = Ph[ra]; ah[m][1] = Ph[rb];
                ah[m][2] = Ph[ra + 4]; ah[m][3] = Ph[rb + 4];
            }
            #pragma unroll
            for (int n = 0; n < 8; n++) {
                int e = e0 + 8 * n + g;
                int vb = e * 36 + kb2 + tig;
                uint32_t bh0 = Vh[vb], bh1 = Vh[vb + 4];
                #pragma unroll
                for (int m = 0; m < 2; m++) {
                    mma_f16(acc[m][n], ah[m][0], ah[m][1], ah[m][2], ah[m][3], bh0, bh1);
                }
            }
        }
    }

    // partial O store to this half's buffer
    float* op = g_Op + (size_t)jh * OSZ;
    #pragma unroll
    for (int m = 0; m < 2; m++)
        #pragma unroll
        for (int n = 0; n < 8; n++) {
            int e = e0 + 8 * n + 2 * tig;
            if (e < DD) {
                int i = i0 + m0 + 16 * m + g;
                *(float2*)&op[((size_t)(b * N1C + i)) * DD + e] =
                    make_float2(acc[m][n][0], acc[m][n][1]);
                *(float2*)&op[((size_t)(b * N1C + i + 8)) * DD + e] =
                    make_float2(acc[m][n][2], acc[m][n][3]);
            }
        }
}

// ================= kernel 4: merge the two O halves =================
__global__ __launch_bounds__(256) void omerge_kernel(float* __restrict__ out)
{
    size_t idx = ((size_t)blockIdx.x * 256 + threadIdx.x) * 4;
    if (idx < OSZ) {
        float4 a = *(const float4*)&g_Op[idx];
        float4 c = *(const float4*)&g_Op[OSZ + idx];
        a.x += c.x; a.y += c.y; a.z += c.z; a.w += c.w;
        *(float4*)&out[idx] = a;
    }
}

// ================= launch =================
extern "C" void kernel_launch(void* const* d_in, const int* in_sizes, int n_in,
                              void* d_out, int out_size)
{
    const float* x1  = (const float*)d_in[0];
    const float* x2  = (const float*)d_in[1];
    const int*   msk = (const int*)  d_in[2];
    const float* Wq  = (const float*)d_in[3];
    const float* Wk  = (const float*)d_in[4];
    const float* Wv  = (const float*)d_in[5];

    float* outO = (float*)d_out;                    // [B,N1,D]
    float* outP = outO + OSZ;                       // [B,N1,N2]

    cudaFuncSetAttribute(proj_kernel,  cudaFuncAttributeMaxDynamicSharedMemorySize, PJ_SMEM);
    cudaFuncSetAttribute(score_kernel, cudaFuncAttributeMaxDynamicSharedMemorySize, SC_SMEM);
    cudaFuncSetAttribute(pv_kernel,    cudaFuncAttributeMaxDynamicSharedMemorySize, PV_SMEM);

    proj_kernel <<<dim3(NROWS / 64, 3), 256, PJ_SMEM>>>(x1, x2, Wq, Wk, Wv);
    score_kernel<<<dim3(N1C / 128, BB, 2), 256, SC_SMEM>>>(msk);
    pv_kernel   <<<dim3(N1C / 128, BB, 2), 256, PV_SMEM>>>(outP);
    omerge_kernel<<<(int)((OSZ / 4 + 255) / 256), 256>>>(outO);
}